// round 7
// baseline (speedup 1.0000x reference)
#include <cuda_runtime.h>
#include <cuda_fp16.h>
#include <stdint.h>

// SplineConv: N=100000, E=1.6M, DIM=2, K=5, deg-1 open spline, M_in=M_out=32, K_TOT=25.
#define MAXN 100000
#define MAXE 1600000
#define KTOT 25
#define KM   800    // KTOT*32 Z-channels per node
#define NBKT 1024   // row buckets (row >> 7): 782 used for N=100000
#define RB   128    // rows per bucket

// ---------------- device scratch (allocation-free) ----------------
__device__ __half g_Zh[(size_t)MAXN * KM];   // 160 MB fp16 Z[n, p]  (p = k*32+o)
__device__ __half g_Wh[KTOT * 32 * 32];      // [p=800][i=32] f16  (B operand)
__device__ uint4  g_edesc[MAXE];             // packed edges: {row, col|kidx<<20, fx, fy}
__device__ uint4  g_edesc2[MAXE];            // row-bucket-sorted descriptors
__device__ int    g_hist[NBKT];
__device__ int    g_start[NBKT];             // exclusive prefix (preserved)
__device__ int    g_off[NBKT];               // scatter cursor (mutated)
__device__ int    g_is64;

__device__ __forceinline__ uint32_t smem_u32(const void* p) {
    uint32_t a;
    asm("{ .reg .u64 t; cvta.to.shared.u64 t, %1; cvt.u32.u64 %0, t; }" : "=r"(a) : "l"(p));
    return a;
}
__device__ __forceinline__ void ldsm_x4(uint32_t addr, uint32_t* r) {
    asm volatile("ldmatrix.sync.aligned.m8n8.x4.shared.b16 {%0,%1,%2,%3}, [%4];"
        : "=r"(r[0]), "=r"(r[1]), "=r"(r[2]), "=r"(r[3]) : "r"(addr));
}
__device__ __forceinline__ void mma16816(float* d, const uint32_t* a, uint32_t b0, uint32_t b1) {
    asm volatile("mma.sync.aligned.m16n8k16.row.col.f32.f16.f16.f32 "
        "{%0,%1,%2,%3}, {%4,%5,%6,%7}, {%8,%9}, {%0,%1,%2,%3};"
        : "+f"(d[0]), "+f"(d[1]), "+f"(d[2]), "+f"(d[3])
        : "r"(a[0]), "r"(a[1]), "r"(a[2]), "r"(a[3]), "r"(b0), "r"(b1));
}
__device__ __forceinline__ uint32_t packh2(float lo, float hi) {
    uint32_t r;
    asm("cvt.rn.f16x2.f32 %0, %1, %2;" : "=r"(r) : "f"(hi), "f"(lo));
    return r;
}

// ---------------- dtype detection + histogram zero ----------------
__global__ void k_detect(const unsigned int* __restrict__ w, int nwords) {
    __shared__ int nz;
    if (threadIdx.x == 0) nz = 0;
    for (int i = threadIdx.x; i < NBKT; i += blockDim.x) g_hist[i] = 0;
    __syncthreads();
    int lim = nwords < 4096 ? nwords : 4096;
    int any = 0;
    for (int i = 1 + 2 * (int)threadIdx.x; i < lim; i += 2 * (int)blockDim.x)
        if (w[i] != 0u) any = 1;
    if (any) atomicOr(&nz, 1);
    __syncthreads();
    if (threadIdx.x == 0) g_is64 = (nz == 0) ? 1 : 0;
}

// ---------------- edge preprocessing: pack descriptor + row-bucket histogram ----------------
__global__ __launch_bounds__(256)
void k_eprep(const void* __restrict__ ei, const float* __restrict__ pseudo, int E) {
    int e = blockIdx.x * blockDim.x + threadIdx.x;
    if (e >= E) return;
    int r, c;
    if (g_is64) {
        const long long* p = (const long long*)ei;
        r = (int)p[e]; c = (int)p[(size_t)E + e];
    } else {
        const int* p = (const int*)ei;
        r = p[e]; c = p[E + e];
    }
    float2 ps = ((const float2*)pseudo)[e];
    float px = ps.x * 4.0f, py = ps.y * 4.0f;   // scale = K-1 (open spline)
    float lx = fminf(fmaxf(floorf(px), 0.0f), 3.0f);
    float ly = fminf(fmaxf(floorf(py), 0.0f), 3.0f);
    int kidx = (int)ly * 5 + (int)lx;           // 0..18
    g_edesc[e] = make_uint4((uint32_t)r,
                            (uint32_t)c | ((uint32_t)kidx << 20),
                            __float_as_uint(px - lx),
                            __float_as_uint(py - ly));
    atomicAdd(&g_hist[r >> 7], 1);
}

// ---------------- exclusive scan of bucket histogram (1 block, 1024 thr) ----------------
__global__ void k_scan() {
    __shared__ int s[NBKT];
    int t = threadIdx.x;
    int h = g_hist[t];
    s[t] = h;
    __syncthreads();
    for (int off = 1; off < NBKT; off <<= 1) {
        int v = (t >= off) ? s[t - off] : 0;
        __syncthreads();
        s[t] += v;
        __syncthreads();
    }
    g_start[t] = s[t] - h;   // exclusive prefix (preserved for edge ranges)
    g_off[t]   = s[t] - h;   // scatter cursor
}

// ---------------- scatter: counting-sort descriptors by row bucket ----------------
__global__ __launch_bounds__(256)
void k_scatter(int E) {
    int e = blockIdx.x * blockDim.x + threadIdx.x;
    if (e >= E) return;
    uint4 d = g_edesc[e];
    int pos = atomicAdd(&g_off[d.x >> 7], 1);
    g_edesc2[pos] = d;
}

// ---------------- W transpose+convert: g_Wh[p][i] = W[k,i,o], p=k*32+o ----------------
__global__ void k_prep(const float* __restrict__ w) {
    int t = blockIdx.x * blockDim.x + threadIdx.x;
    if (t >= KTOT * 1024) return;
    int p = t >> 5, i = t & 31;
    int k = p >> 5, o = p & 31;
    g_Wh[t] = __float2half(w[k * 1024 + i * 32 + o]);
}

// ---------------- Z = x @ Wt via mma.sync m16n8k16, split-N over gridDim.y ----------------
#define NB_COLS 400
#define SB_OFF  10240                    // A: 128*80
#define ZG_SMEM (10240 + NB_COLS * 80)   // + B: 400*80 = 42240

__global__ __launch_bounds__(256, 4)
void k_zgemm_mma(const float* __restrict__ x, int N) {
    extern __shared__ __align__(128) char smem[];
    char* sA = smem;
    char* sB = smem + SB_OFF;
    int tid = threadIdx.x;
    int n0 = blockIdx.x * 128;
    int colbase = blockIdx.y * NB_COLS;

    for (int g = tid; g < NB_COLS * 4; g += 256) {
        int row = g >> 2, sub = g & 3;
        *(uint4*)(sB + row * 80 + sub * 16) =
            *(const uint4*)(g_Wh + (colbase + row) * 32 + sub * 8);
    }
    for (int g = tid; g < 512; g += 256) {
        int row = g >> 2, sub = g & 3;
        int n = n0 + row;
        uint4 hv = make_uint4(0, 0, 0, 0);
        if (n < N) {
            const float4* xp = (const float4*)(x + (size_t)n * 32 + sub * 8);
            float4 a = xp[0], b = xp[1];
            hv.x = packh2(a.x, a.y);
            hv.y = packh2(a.z, a.w);
            hv.z = packh2(b.x, b.y);
            hv.w = packh2(b.z, b.w);
        }
        *(uint4*)(sA + row * 80 + sub * 16) = hv;
    }
    __syncthreads();

    int wid = tid >> 5, lane = tid & 31;
    int m0 = wid * 16;
    int r = lane & 7, sel = lane >> 3;

    uint32_t aaddr = smem_u32(sA + (m0 + r + ((sel & 1) ? 8 : 0)) * 80 + (sel >> 1) * 16);
    uint32_t a[8];
    ldsm_x4(aaddr,      a);
    ldsm_x4(aaddr + 32, a + 4);

    uint32_t sBu  = smem_u32(sB);
    uint32_t bofs = (r + ((sel >> 1) ? 8 : 0)) * 80 + (sel & 1) * 16;

    int mrow  = lane >> 2;
    int ncol0 = (lane & 3) * 2;
    int node_lo = n0 + m0 + mrow;
    int node_hi = node_lo + 8;
    __half* z_lo = g_Zh + (size_t)node_lo * KM + colbase;
    __half* z_hi = g_Zh + (size_t)node_hi * KM + colbase;
    bool ok_lo = node_lo < N, ok_hi = node_hi < N;

    for (int nb = 0; nb < NB_COLS; nb += 16) {
        uint32_t baddr = sBu + nb * 80 + bofs;
        uint32_t b[8];
        ldsm_x4(baddr,      b);
        ldsm_x4(baddr + 32, b + 4);

        float acc0[4] = {0.f, 0.f, 0.f, 0.f};
        float acc1[4] = {0.f, 0.f, 0.f, 0.f};
        mma16816(acc0, a,     b[0], b[1]);
        mma16816(acc0, a + 4, b[4], b[5]);
        mma16816(acc1, a,     b[2], b[3]);
        mma16816(acc1, a + 4, b[6], b[7]);

        if (ok_lo) {
            *(uint32_t*)(z_lo + nb + ncol0)     = packh2(acc0[0], acc0[1]);
            *(uint32_t*)(z_lo + nb + 8 + ncol0) = packh2(acc1[0], acc1[1]);
        }
        if (ok_hi) {
            *(uint32_t*)(z_hi + nb + ncol0)     = packh2(acc0[2], acc0[3]);
            *(uint32_t*)(z_hi + nb + 8 + ncol0) = packh2(acc1[2], acc1[3]);
        }
    }
}

// ---------------- fused edge + finalize: one block per 128-row bucket ----------------
// Accumulates the bucket's out slab + degree in SMEM (no global atomics),
// then applies mean-divide + root term + bias and writes out once, coalesced.
#define EB 4
__global__ __launch_bounds__(256)
void k_edge_row(const float* __restrict__ x, const float* __restrict__ rootw,
                const float* __restrict__ bias, float* __restrict__ out, int N) {
    __shared__ float slab[RB * 32];   // 16 KB accumulator
    __shared__ float sdeg[RB];
    __shared__ float sR[1024];
    __shared__ float sB[32];

    int b   = blockIdx.x;
    int tid = threadIdx.x;
    int lane = tid & 31, wid = tid >> 5;

    for (int i = tid; i < RB * 32; i += 256) slab[i] = 0.0f;
    for (int i = tid; i < RB; i += 256)      sdeg[i] = 0.0f;
    for (int i = tid; i < 1024; i += 256)    sR[i] = rootw[i];
    if (tid < 32) sB[tid] = bias[tid];
    __syncthreads();

    int start = g_start[b];
    int end   = start + g_hist[b];
    int rbase = b * RB;

    for (int q = start + wid * EB; q < end; q += 8 * EB) {
        uint4 d[EB];
#pragma unroll
        for (int j = 0; j < EB; j++) {
            int e = q + j; if (e > end - 1) e = end - 1;
            d[j] = g_edesc2[e];                      // sequential 16B broadcast
        }
        float z[EB][4];
#pragma unroll
        for (int j = 0; j < EB; j++) {
            uint32_t cp = d[j].y;
            const __half* zb = g_Zh + (size_t)(cp & 0xFFFFFu) * KM
                             + ((cp >> 20) << 5) + lane;
            z[j][0] = __half2float(zb[0]);     // tap (ix  , iy  )
            z[j][1] = __half2float(zb[32]);    // tap (ix+1, iy  )
            z[j][2] = __half2float(zb[160]);   // tap (ix  , iy+1)
            z[j][3] = __half2float(zb[192]);   // tap (ix+1, iy+1)
        }
#pragma unroll
        for (int j = 0; j < EB; j++) {
            if (q + j < end) {
                float fx = __uint_as_float(d[j].z);
                float fy = __uint_as_float(d[j].w);
                float v = (1.0f - fy) * ((1.0f - fx) * z[j][0] + fx * z[j][1])
                        +         fy  * ((1.0f - fx) * z[j][2] + fx * z[j][3]);
                int rl = (int)d[j].x - rbase;
                atomicAdd(&slab[rl * 32 + lane], v);     // SMEM atomic, bank-spread
                if (lane == 0) atomicAdd(&sdeg[rl], 1.0f);
            }
        }
    }
    __syncthreads();

    // finalize: warp per row
    for (int r = wid; r < RB; r += 8) {
        int n = rbase + r;
        if (n >= N) break;
        float xv  = x[(size_t)n * 32 + lane];
        float acc = 0.0f;
#pragma unroll
        for (int i = 0; i < 32; i++) {
            float xi = __shfl_sync(0xffffffffu, xv, i);
            acc += xi * sR[i * 32 + lane];
        }
        float dgg = fmaxf(sdeg[r], 1.0f);
        out[(size_t)n * 32 + lane] = slab[r * 32 + lane] / dgg + acc + sB[lane];
    }
}

// ---------------- launch ----------------
extern "C" void kernel_launch(void* const* d_in, const int* in_sizes, int n_in,
                              void* d_out, int out_size) {
    const float* x      = (const float*)d_in[0];
    const void*  ei     = d_in[1];
    const float* pseudo = (const float*)d_in[2];
    const float* weight = (const float*)d_in[3];
    const float* rootw  = (const float*)d_in[4];
    const float* bias   = (const float*)d_in[5];
    float*       out    = (float*)d_out;

    int N = in_sizes[0] / 32;
    int E = in_sizes[2] / 2;
    int nbuckets = (N + RB - 1) / RB;

    k_detect<<<1, 256>>>((const unsigned int*)ei, 2 * E);
    k_eprep<<<(E + 255) / 256, 256>>>(ei, pseudo, E);
    k_scan<<<1, NBKT>>>();
    k_scatter<<<(E + 255) / 256, 256>>>(E);

    k_prep<<<(KTOT * 1024 + 255) / 256, 256>>>(weight);
    cudaFuncSetAttribute(k_zgemm_mma, cudaFuncAttributeMaxDynamicSharedMemorySize, ZG_SMEM);
    dim3 zg((N + 127) / 128, 2);
    k_zgemm_mma<<<zg, 256, ZG_SMEM>>>(x, N);

    k_edge_row<<<nbuckets, 256>>>(x, rootw, bias, out, N);
}

// round 9
// speedup vs baseline: 1.9154x; 1.9154x over previous
#include <cuda_runtime.h>
#include <cuda_fp16.h>
#include <stdint.h>

// SplineConv: N=100000, E=1.6M, DIM=2, K=5, deg-1 open spline, M_in=M_out=32, K_TOT=25.
#define MAXN 100000
#define MAXE 1600000
#define KTOT 25
#define KM   800      // KTOT*32 Z-channels per node
#define NB2  32768    // sort buckets (col >> 2): 25000 used; spread enough for atomics

// ---------------- device scratch (allocation-free) ----------------
__device__ __half g_Zh[(size_t)MAXN * KM];   // 160 MB fp16 Z[n, p]  (p = k*32+o)
__device__ __half g_Wh[KTOT * 32 * 32];      // [p=800][i=32] f16  (B operand)
__device__ uint4  g_edesc[MAXE];             // packed edges: {row, col|kidx<<20, fx, fy}
__device__ uint4  g_edesc2[MAXE];            // col-sorted descriptors
__device__ int    g_hist2[NB2];
__device__ int    g_off2[NB2];               // scatter cursors (exclusive prefix, mutated)
__device__ float  g_deg[MAXN];
__device__ int    g_is64;

__device__ __forceinline__ uint32_t smem_u32(const void* p) {
    uint32_t a;
    asm("{ .reg .u64 t; cvta.to.shared.u64 t, %1; cvt.u32.u64 %0, t; }" : "=r"(a) : "l"(p));
    return a;
}
__device__ __forceinline__ void ldsm_x4(uint32_t addr, uint32_t* r) {
    asm volatile("ldmatrix.sync.aligned.m8n8.x4.shared.b16 {%0,%1,%2,%3}, [%4];"
        : "=r"(r[0]), "=r"(r[1]), "=r"(r[2]), "=r"(r[3]) : "r"(addr));
}
__device__ __forceinline__ void mma16816(float* d, const uint32_t* a, uint32_t b0, uint32_t b1) {
    asm volatile("mma.sync.aligned.m16n8k16.row.col.f32.f16.f16.f32 "
        "{%0,%1,%2,%3}, {%4,%5,%6,%7}, {%8,%9}, {%0,%1,%2,%3};"
        : "+f"(d[0]), "+f"(d[1]), "+f"(d[2]), "+f"(d[3])
        : "r"(a[0]), "r"(a[1]), "r"(a[2]), "r"(a[3]), "r"(b0), "r"(b1));
}
__device__ __forceinline__ uint32_t packh2(float lo, float hi) {
    uint32_t r;
    asm("cvt.rn.f16x2.f32 %0, %1, %2;" : "=r"(r) : "f"(hi), "f"(lo));
    return r;
}
// streaming loads (.cs = evict-first in L1 and L2): keep out accumulator hot in L2
__device__ __forceinline__ float ldh_stream(const __half* p) {
    unsigned short v;
    asm volatile("ld.global.cs.u16 %0, [%1];" : "=h"(v) : "l"(p));
    return __half2float(__ushort_as_half(v));
}
__device__ __forceinline__ uint4 ld4_stream(const uint4* p) {
    uint4 v;
    asm volatile("ld.global.cs.v4.u32 {%0,%1,%2,%3}, [%4];"
        : "=r"(v.x), "=r"(v.y), "=r"(v.z), "=r"(v.w) : "l"(p));
    return v;
}

// ---------------- dtype detection ----------------
__global__ void k_detect(const unsigned int* __restrict__ w, int nwords) {
    __shared__ int nz;
    if (threadIdx.x == 0) nz = 0;
    __syncthreads();
    int lim = nwords < 4096 ? nwords : 4096;
    int any = 0;
    for (int i = 1 + 2 * (int)threadIdx.x; i < lim; i += 2 * (int)blockDim.x)
        if (w[i] != 0u) any = 1;
    if (any) atomicOr(&nz, 1);
    __syncthreads();
    if (threadIdx.x == 0) g_is64 = (nz == 0) ? 1 : 0;
}

// ---------------- zero: out + degree + bucket histogram ----------------
__global__ void k_zero(float* __restrict__ out, int nout, int ndeg) {
    int i = blockIdx.x * blockDim.x + threadIdx.x;
    if (i < nout)                   out[i] = 0.0f;
    else if (i < nout + ndeg)       g_deg[i - nout] = 0.0f;
    else if (i < nout + ndeg + NB2) g_hist2[i - nout - ndeg] = 0;
}

// ---------------- edge preprocessing: pack descriptor + degree + fine hist ----------------
__global__ __launch_bounds__(256)
void k_eprep(const void* __restrict__ ei, const float* __restrict__ pseudo, int E) {
    int e = blockIdx.x * blockDim.x + threadIdx.x;
    if (e >= E) return;
    int r, c;
    if (g_is64) {
        const long long* p = (const long long*)ei;
        r = (int)p[e]; c = (int)p[(size_t)E + e];
    } else {
        const int* p = (const int*)ei;
        r = p[e]; c = p[E + e];
    }
    float2 ps = ((const float2*)pseudo)[e];
    float px = ps.x * 4.0f, py = ps.y * 4.0f;   // scale = K-1 (open spline)
    float lx = fminf(fmaxf(floorf(px), 0.0f), 3.0f);
    float ly = fminf(fmaxf(floorf(py), 0.0f), 3.0f);
    int kidx = (int)ly * 5 + (int)lx;           // 0..18
    g_edesc[e] = make_uint4((uint32_t)r,
                            (uint32_t)c | ((uint32_t)kidx << 20),
                            __float_as_uint(px - lx),
                            __float_as_uint(py - ly));
    atomicAdd(&g_deg[r], 1.0f);                 // 100k addresses: spread, cheap
    atomicAdd(&g_hist2[c >> 2], 1);             // 25k addresses: spread, cheap
}

// ---------------- exclusive scan of 32768-bucket histogram (1 block) ----------------
__global__ void k_scan2() {
    __shared__ int wsum[32];
    int t = threadIdx.x;           // 1024 threads, 32 buckets each
    int v[32];
    int tot = 0;
#pragma unroll
    for (int i = 0; i < 32; i++) { v[i] = g_hist2[t * 32 + i]; tot += v[i]; }

    int lane = t & 31, wid = t >> 5;
    int s = tot;
#pragma unroll
    for (int o = 1; o < 32; o <<= 1) {
        int u = __shfl_up_sync(0xffffffffu, s, o);
        if (lane >= o) s += u;
    }
    if (lane == 31) wsum[wid] = s;
    __syncthreads();
    if (wid == 0) {
        int ws = (lane < 32) ? wsum[lane] : 0;
#pragma unroll
        for (int o = 1; o < 32; o <<= 1) {
            int u = __shfl_up_sync(0xffffffffu, ws, o);
            if (lane >= o) ws += u;
        }
        wsum[lane] = ws;
    }
    __syncthreads();
    int base = s - tot + (wid > 0 ? wsum[wid - 1] : 0);   // exclusive prefix
#pragma unroll
    for (int i = 0; i < 32; i++) { g_off2[t * 32 + i] = base; base += v[i]; }
}

// ---------------- scatter: counting-sort descriptors by col>>2 bucket ----------------
__global__ __launch_bounds__(256)
void k_scatter(int E) {
    int e = blockIdx.x * blockDim.x + threadIdx.x;
    if (e >= E) return;
    uint4 d = g_edesc[e];
    int pos = atomicAdd(&g_off2[(d.y & 0xFFFFFu) >> 2], 1);
    g_edesc2[pos] = d;
}

// ---------------- W transpose+convert: g_Wh[p][i] = W[k,i,o], p=k*32+o ----------------
__global__ void k_prep(const float* __restrict__ w) {
    int t = blockIdx.x * blockDim.x + threadIdx.x;
    if (t >= KTOT * 1024) return;
    int p = t >> 5, i = t & 31;
    int k = p >> 5, o = p & 31;
    g_Wh[t] = __float2half(w[k * 1024 + i * 32 + o]);
}

// ---------------- Z = x @ Wt via mma.sync m16n8k16, split-N over gridDim.y ----------------
#define NB_COLS 400
#define SB_OFF  10240                    // A: 128*80
#define ZG_SMEM (10240 + NB_COLS * 80)   // + B: 400*80 = 42240

__global__ __launch_bounds__(256, 4)
void k_zgemm_mma(const float* __restrict__ x, int N) {
    extern __shared__ __align__(128) char smem[];
    char* sA = smem;
    char* sB = smem + SB_OFF;
    int tid = threadIdx.x;
    int n0 = blockIdx.x * 128;
    int colbase = blockIdx.y * NB_COLS;

    for (int g = tid; g < NB_COLS * 4; g += 256) {
        int row = g >> 2, sub = g & 3;
        *(uint4*)(sB + row * 80 + sub * 16) =
            *(const uint4*)(g_Wh + (colbase + row) * 32 + sub * 8);
    }
    for (int g = tid; g < 512; g += 256) {
        int row = g >> 2, sub = g & 3;
        int n = n0 + row;
        uint4 hv = make_uint4(0, 0, 0, 0);
        if (n < N) {
            const float4* xp = (const float4*)(x + (size_t)n * 32 + sub * 8);
            float4 a = xp[0], b = xp[1];
            hv.x = packh2(a.x, a.y);
            hv.y = packh2(a.z, a.w);
            hv.z = packh2(b.x, b.y);
            hv.w = packh2(b.z, b.w);
        }
        *(uint4*)(sA + row * 80 + sub * 16) = hv;
    }
    __syncthreads();

    int wid = tid >> 5, lane = tid & 31;
    int m0 = wid * 16;
    int r = lane & 7, sel = lane >> 3;

    uint32_t aaddr = smem_u32(sA + (m0 + r + ((sel & 1) ? 8 : 0)) * 80 + (sel >> 1) * 16);
    uint32_t a[8];
    ldsm_x4(aaddr,      a);
    ldsm_x4(aaddr + 32, a + 4);

    uint32_t sBu  = smem_u32(sB);
    uint32_t bofs = (r + ((sel >> 1) ? 8 : 0)) * 80 + (sel & 1) * 16;

    int mrow  = lane >> 2;
    int ncol0 = (lane & 3) * 2;
    int node_lo = n0 + m0 + mrow;
    int node_hi = node_lo + 8;
    __half* z_lo = g_Zh + (size_t)node_lo * KM + colbase;
    __half* z_hi = g_Zh + (size_t)node_hi * KM + colbase;
    bool ok_lo = node_lo < N, ok_hi = node_hi < N;

    for (int nb = 0; nb < NB_COLS; nb += 16) {
        uint32_t baddr = sBu + nb * 80 + bofs;
        uint32_t b[8];
        ldsm_x4(baddr,      b);
        ldsm_x4(baddr + 32, b + 4);

        float acc0[4] = {0.f, 0.f, 0.f, 0.f};
        float acc1[4] = {0.f, 0.f, 0.f, 0.f};
        mma16816(acc0, a,     b[0], b[1]);
        mma16816(acc0, a + 4, b[4], b[5]);
        mma16816(acc1, a,     b[2], b[3]);
        mma16816(acc1, a + 4, b[6], b[7]);

        if (ok_lo) {
            *(uint32_t*)(z_lo + nb + ncol0)     = packh2(acc0[0], acc0[1]);
            *(uint32_t*)(z_lo + nb + 8 + ncol0) = packh2(acc1[0], acc1[1]);
        }
        if (ok_hi) {
            *(uint32_t*)(z_hi + nb + ncol0)     = packh2(acc0[2], acc0[3]);
            *(uint32_t*)(z_hi + nb + 8 + ncol0) = packh2(acc1[2], acc1[3]);
        }
    }
}

// ---------------- edge phase: col-sorted stream, .cs gathers, L2-resident REDs ----------------
#define EB 6
__global__ __launch_bounds__(256, 3)
void k_edge(float* __restrict__ out, int E) {
    int lane   = threadIdx.x & 31;
    int warp   = (blockIdx.x * blockDim.x + threadIdx.x) >> 5;
    int nwarps = (gridDim.x * blockDim.x) >> 5;

    for (int q = warp * EB; q < E; q += nwarps * EB) {
        uint4 d[EB];
#pragma unroll
        for (int j = 0; j < EB; j++) {
            int e = q + j; if (e > E - 1) e = E - 1;
            d[j] = ld4_stream(&g_edesc2[e]);         // sequential, read-once
        }
        float z[EB][4];
#pragma unroll
        for (int j = 0; j < EB; j++) {
            uint32_t cp = d[j].y;
            const __half* zb = g_Zh + (size_t)(cp & 0xFFFFFu) * KM
                             + ((cp >> 20) << 5) + lane;
            z[j][0] = ldh_stream(zb);          // tap (ix  , iy  )
            z[j][1] = ldh_stream(zb + 32);     // tap (ix+1, iy  )
            z[j][2] = ldh_stream(zb + 160);    // tap (ix  , iy+1)
            z[j][3] = ldh_stream(zb + 192);    // tap (ix+1, iy+1)
        }
#pragma unroll
        for (int j = 0; j < EB; j++) {
            if (q + j < E) {
                float fx = __uint_as_float(d[j].z);
                float fy = __uint_as_float(d[j].w);
                float v = (1.0f - fy) * ((1.0f - fx) * z[j][0] + fx * z[j][1])
                        +         fy  * ((1.0f - fx) * z[j][2] + fx * z[j][3]);
                atomicAdd(out + (size_t)d[j].x * 32 + lane, v);
            }
        }
    }
}

// ---------------- finalize: mean-divide + root term + bias ----------------
__global__ __launch_bounds__(256)
void k_final(const float* __restrict__ x, const float* __restrict__ rootw,
             const float* __restrict__ bias, float* __restrict__ out, int N) {
    __shared__ float sR[1024];
    __shared__ float sB[32];
    for (int i = threadIdx.x; i < 1024; i += blockDim.x) sR[i] = rootw[i];
    if (threadIdx.x < 32) sB[threadIdx.x] = bias[threadIdx.x];
    __syncthreads();

    int gid = blockIdx.x * blockDim.x + threadIdx.x;
    if (gid >= N * 32) return;
    int n = gid >> 5, o = gid & 31;

    float xv  = x[gid];
    float acc = 0.0f;
#pragma unroll
    for (int i = 0; i < 32; i++) {
        float xi = __shfl_sync(0xffffffffu, xv, i);
        acc += xi * sR[i * 32 + o];
    }
    float dgg = fmaxf(g_deg[n], 1.0f);
    out[gid] = out[gid] / dgg + acc + sB[o];
}

// ---------------- launch ----------------
extern "C" void kernel_launch(void* const* d_in, const int* in_sizes, int n_in,
                              void* d_out, int out_size) {
    const float* x      = (const float*)d_in[0];
    const void*  ei     = d_in[1];
    const float* pseudo = (const float*)d_in[2];
    const float* weight = (const float*)d_in[3];
    const float* rootw  = (const float*)d_in[4];
    const float* bias   = (const float*)d_in[5];
    float*       out    = (float*)d_out;

    int N = in_sizes[0] / 32;
    int E = in_sizes[2] / 2;

    k_detect<<<1, 256>>>((const unsigned int*)ei, 2 * E);

    int ztot = N * 32 + N + NB2;
    k_zero<<<(ztot + 255) / 256, 256>>>(out, N * 32, N);

    k_eprep<<<(E + 255) / 256, 256>>>(ei, pseudo, E);
    k_scan2<<<1, 1024>>>();
    k_scatter<<<(E + 255) / 256, 256>>>(E);

    k_prep<<<(KTOT * 1024 + 255) / 256, 256>>>(weight);
    cudaFuncSetAttribute(k_zgemm_mma, cudaFuncAttributeMaxDynamicSharedMemorySize, ZG_SMEM);
    dim3 zg((N + 127) / 128, 2);
    k_zgemm_mma<<<zg, 256, ZG_SMEM>>>(x, N);

    k_edge<<<2048, 256>>>(out, E);

    k_final<<<(N * 32 + 255) / 256, 256>>>(x, rootw, bias, out, N);
}

// round 11
// speedup vs baseline: 2.3185x; 1.2104x over previous
#include <cuda_runtime.h>
#include <cuda_fp16.h>
#include <stdint.h>

// SplineConv: N=100000, E=1.6M, DIM=2, K=5, deg-1 open spline, M_in=M_out=32, K_TOT=25.
#define MAXN 100000
#define MAXE 1600000
#define KTOT 25
#define KM   800    // KTOT*32 Z-channels per node

// ---------------- device scratch (allocation-free) ----------------
__device__ __half g_Zh[(size_t)MAXN * KM];   // 160 MB fp16 Z[n, p]  (p = k*32+o)
__device__ __half g_Wh[KTOT * 32 * 32];      // [p=800][i=32] f16  (B operand)
__device__ uint4  g_edesc2[MAXE];            // row-sorted descriptors {col|kidx<<20, fx, fy, 0}
__device__ int    g_histN[MAXN + 1];         // per-node in-degree
__device__ int    g_startN[MAXN + 1];        // CSR offsets (exclusive prefix)
__device__ int    g_offN[MAXN + 1];          // scatter cursors
__device__ int    g_bsum[256];               // scan block sums
__device__ int    g_bpre[256];               // scanned block sums (exclusive)
__device__ int    g_is64;

__device__ __forceinline__ uint32_t smem_u32(const void* p) {
    uint32_t a;
    asm("{ .reg .u64 t; cvta.to.shared.u64 t, %1; cvt.u32.u64 %0, t; }" : "=r"(a) : "l"(p));
    return a;
}
__device__ __forceinline__ void ldsm_x4(uint32_t addr, uint32_t* r) {
    asm volatile("ldmatrix.sync.aligned.m8n8.x4.shared.b16 {%0,%1,%2,%3}, [%4];"
        : "=r"(r[0]), "=r"(r[1]), "=r"(r[2]), "=r"(r[3]) : "r"(addr));
}
__device__ __forceinline__ void mma16816(float* d, const uint32_t* a, uint32_t b0, uint32_t b1) {
    asm volatile("mma.sync.aligned.m16n8k16.row.col.f32.f16.f16.f32 "
        "{%0,%1,%2,%3}, {%4,%5,%6,%7}, {%8,%9}, {%0,%1,%2,%3};"
        : "+f"(d[0]), "+f"(d[1]), "+f"(d[2]), "+f"(d[3])
        : "r"(a[0]), "r"(a[1]), "r"(a[2]), "r"(a[3]), "r"(b0), "r"(b1));
}
__device__ __forceinline__ uint32_t packh2(float lo, float hi) {
    uint32_t r;
    asm("cvt.rn.f16x2.f32 %0, %1, %2;" : "=r"(r) : "f"(hi), "f"(lo));
    return r;
}

// ---------------- dtype detection ----------------
__global__ void k_detect(const unsigned int* __restrict__ w, int nwords) {
    __shared__ int nz;
    if (threadIdx.x == 0) nz = 0;
    __syncthreads();
    int lim = nwords < 4096 ? nwords : 4096;
    int any = 0;
    for (int i = 1 + 2 * (int)threadIdx.x; i < lim; i += 2 * (int)blockDim.x)
        if (w[i] != 0u) any = 1;
    if (any) atomicOr(&nz, 1);
    __syncthreads();
    if (threadIdx.x == 0) g_is64 = (nz == 0) ? 1 : 0;
}

// ---------------- zero per-node histogram ----------------
__global__ void k_zeroh(int N1) {
    int i = blockIdx.x * blockDim.x + threadIdx.x;
    if (i < N1) g_histN[i] = 0;
}

// ---------------- per-node degree histogram (100k spread atomics) ----------------
__global__ __launch_bounds__(256)
void k_hist(const void* __restrict__ ei, int E) {
    int e = blockIdx.x * blockDim.x + threadIdx.x;
    if (e >= E) return;
    int r;
    if (g_is64) r = (int)((const long long*)ei)[e];
    else        r = ((const int*)ei)[e];
    atomicAdd(&g_histN[r], 1);
}

// ---------------- multi-block scan, pass A: block sums (1024 entries/block) ----------------
__global__ void kA_bsum(int N1) {
    __shared__ int ws[32];
    int t = threadIdx.x;
    int i = blockIdx.x * 1024 + t;
    int v = (i < N1) ? g_histN[i] : 0;
    // warp reduce
    for (int o = 16; o > 0; o >>= 1) v += __shfl_down_sync(0xffffffffu, v, o);
    if ((t & 31) == 0) ws[t >> 5] = v;
    __syncthreads();
    if (t < 32) {
        int s = ws[t];
        for (int o = 16; o > 0; o >>= 1) s += __shfl_down_sync(0xffffffffu, s, o);
        if (t == 0) g_bsum[blockIdx.x] = s;
    }
}

// ---------------- pass B: scan up to 256 block sums (1 block) ----------------
__global__ void kB_scan(int nsb) {
    __shared__ int ws[8];
    int t = threadIdx.x;                    // 256 threads
    int v = (t < nsb) ? g_bsum[t] : 0;
    int lane = t & 31, wid = t >> 5;
    int s = v;
    for (int o = 1; o < 32; o <<= 1) {
        int u = __shfl_up_sync(0xffffffffu, s, o);
        if (lane >= o) s += u;
    }
    if (lane == 31) ws[wid] = s;
    __syncthreads();
    if (wid == 0 && lane < 8) {
        int x2 = ws[lane];
        for (int o = 1; o < 8; o <<= 1) {
            int u = __shfl_up_sync(0xffu, x2, o);
            if (lane >= o) x2 += u;
        }
        ws[lane] = x2;
    }
    __syncthreads();
    int incl = s + (wid > 0 ? ws[wid - 1] : 0);
    if (t < nsb) g_bpre[t] = incl - v;      // exclusive
}

// ---------------- pass C: block-local exclusive scan + global offset ----------------
__global__ void kC_scan(int N1) {
    __shared__ int ws[32];
    int t = threadIdx.x;
    int i = blockIdx.x * 1024 + t;
    int v = (i < N1) ? g_histN[i] : 0;
    int lane = t & 31, wid = t >> 5;
    int s = v;
    for (int o = 1; o < 32; o <<= 1) {
        int u = __shfl_up_sync(0xffffffffu, s, o);
        if (lane >= o) s += u;
    }
    if (lane == 31) ws[wid] = s;
    __syncthreads();
    if (wid == 0) {
        int x2 = ws[lane];
        for (int o = 1; o < 32; o <<= 1) {
            int u = __shfl_up_sync(0xffffffffu, x2, o);
            if (lane >= o) x2 += u;
        }
        ws[lane] = x2;
    }
    __syncthreads();
    int excl = s - v + (wid > 0 ? ws[wid - 1] : 0) + g_bpre[blockIdx.x];
    if (i < N1) { g_startN[i] = excl; g_offN[i] = excl; }
}

// ---------------- scatter: recompute descriptor, counting-sort by row ----------------
__global__ __launch_bounds__(256)
void k_scatter(const void* __restrict__ ei, const float* __restrict__ pseudo, int E) {
    int e = blockIdx.x * blockDim.x + threadIdx.x;
    if (e >= E) return;
    int r, c;
    if (g_is64) {
        const long long* p = (const long long*)ei;
        r = (int)p[e]; c = (int)p[(size_t)E + e];
    } else {
        const int* p = (const int*)ei;
        r = p[e]; c = p[E + e];
    }
    float2 ps = ((const float2*)pseudo)[e];
    float px = ps.x * 4.0f, py = ps.y * 4.0f;   // scale = K-1 (open spline)
    float lx = fminf(fmaxf(floorf(px), 0.0f), 3.0f);
    float ly = fminf(fmaxf(floorf(py), 0.0f), 3.0f);
    int kidx = (int)ly * 5 + (int)lx;           // 0..18
    int pos = atomicAdd(&g_offN[r], 1);         // 100k spread cursors
    g_edesc2[pos] = make_uint4((uint32_t)c | ((uint32_t)kidx << 20),
                               __float_as_uint(px - lx),
                               __float_as_uint(py - ly), 0u);
}

// ---------------- W transpose+convert: g_Wh[p][i] = W[k,i,o], p=k*32+o ----------------
__global__ void k_prep(const float* __restrict__ w) {
    int t = blockIdx.x * blockDim.x + threadIdx.x;
    if (t >= KTOT * 1024) return;
    int p = t >> 5, i = t & 31;
    int k = p >> 5, o = p & 31;
    g_Wh[t] = __float2half(w[k * 1024 + i * 32 + o]);
}

// ---------------- Z = x @ Wt via mma.sync m16n8k16, split-N over gridDim.y ----------------
#define NB_COLS 400
#define SB_OFF  10240                    // A: 128*80
#define ZG_SMEM (10240 + NB_COLS * 80)   // + B: 400*80 = 42240

__global__ __launch_bounds__(256, 4)
void k_zgemm_mma(const float* __restrict__ x, int N) {
    extern __shared__ __align__(128) char smem[];
    char* sA = smem;
    char* sB = smem + SB_OFF;
    int tid = threadIdx.x;
    int n0 = blockIdx.x * 128;
    int colbase = blockIdx.y * NB_COLS;

    for (int g = tid; g < NB_COLS * 4; g += 256) {
        int row = g >> 2, sub = g & 3;
        *(uint4*)(sB + row * 80 + sub * 16) =
            *(const uint4*)(g_Wh + (colbase + row) * 32 + sub * 8);
    }
    for (int g = tid; g < 512; g += 256) {
        int row = g >> 2, sub = g & 3;
        int n = n0 + row;
        uint4 hv = make_uint4(0, 0, 0, 0);
        if (n < N) {
            const float4* xp = (const float4*)(x + (size_t)n * 32 + sub * 8);
            float4 a = xp[0], b = xp[1];
            hv.x = packh2(a.x, a.y);
            hv.y = packh2(a.z, a.w);
            hv.z = packh2(b.x, b.y);
            hv.w = packh2(b.z, b.w);
        }
        *(uint4*)(sA + row * 80 + sub * 16) = hv;
    }
    __syncthreads();

    int wid = tid >> 5, lane = tid & 31;
    int m0 = wid * 16;
    int r = lane & 7, sel = lane >> 3;

    uint32_t aaddr = smem_u32(sA + (m0 + r + ((sel & 1) ? 8 : 0)) * 80 + (sel >> 1) * 16);
    uint32_t a[8];
    ldsm_x4(aaddr,      a);
    ldsm_x4(aaddr + 32, a + 4);

    uint32_t sBu  = smem_u32(sB);
    uint32_t bofs = (r + ((sel >> 1) ? 8 : 0)) * 80 + (sel & 1) * 16;

    int mrow  = lane >> 2;
    int ncol0 = (lane & 3) * 2;
    int node_lo = n0 + m0 + mrow;
    int node_hi = node_lo + 8;
    __half* z_lo = g_Zh + (size_t)node_lo * KM + colbase;
    __half* z_hi = g_Zh + (size_t)node_hi * KM + colbase;
    bool ok_lo = node_lo < N, ok_hi = node_hi < N;

    for (int nb = 0; nb < NB_COLS; nb += 16) {
        uint32_t baddr = sBu + nb * 80 + bofs;
        uint32_t b[8];
        ldsm_x4(baddr,      b);
        ldsm_x4(baddr + 32, b + 4);

        float acc0[4] = {0.f, 0.f, 0.f, 0.f};
        float acc1[4] = {0.f, 0.f, 0.f, 0.f};
        mma16816(acc0, a,     b[0], b[1]);
        mma16816(acc0, a + 4, b[4], b[5]);
        mma16816(acc1, a,     b[2], b[3]);
        mma16816(acc1, a + 4, b[6], b[7]);

        if (ok_lo) {
            *(uint32_t*)(z_lo + nb + ncol0)     = packh2(acc0[0], acc0[1]);
            *(uint32_t*)(z_lo + nb + 8 + ncol0) = packh2(acc1[0], acc1[1]);
        }
        if (ok_hi) {
            *(uint32_t*)(z_hi + nb + ncol0)     = packh2(acc0[2], acc0[3]);
            *(uint32_t*)(z_hi + nb + 8 + ncol0) = packh2(acc1[2], acc1[3]);
        }
    }
}

// ---------------- fused CSR edge + finalize: warp per target node, no atomics ----------------
__global__ __launch_bounds__(256)
void k_edge_csr(const float* __restrict__ x, const float* __restrict__ rootw,
                const float* __restrict__ bias, float* __restrict__ out, int N) {
    __shared__ float sR[1024];
    __shared__ float sB[32];
    int tid = threadIdx.x;
    for (int i = tid; i < 1024; i += 256) sR[i] = rootw[i];
    if (tid < 32) sB[tid] = bias[tid];
    __syncthreads();

    int lane = tid & 31, wid = tid >> 5;
    int n = blockIdx.x * 8 + wid;
    if (n >= N) return;

    int s  = g_startN[n];
    int e2 = g_startN[n + 1];

    float acc = 0.0f;
    for (int q = s; q < e2; q += 4) {
        uint4 dd[4];
#pragma unroll
        for (int j = 0; j < 4; j++) {
            int e = q + j; if (e > e2 - 1) e = e2 - 1;
            dd[j] = g_edesc2[e];                     // sequential 16B broadcast
        }
        float z[4][4];
#pragma unroll
        for (int j = 0; j < 4; j++) {
            uint32_t cp = dd[j].x;
            const __half* zb = g_Zh + (size_t)(cp & 0xFFFFFu) * KM
                             + ((cp >> 20) << 5) + lane;
            z[j][0] = __half2float(zb[0]);     // tap (ix  , iy  )
            z[j][1] = __half2float(zb[32]);    // tap (ix+1, iy  )
            z[j][2] = __half2float(zb[160]);   // tap (ix  , iy+1)
            z[j][3] = __half2float(zb[192]);   // tap (ix+1, iy+1)
        }
#pragma unroll
        for (int j = 0; j < 4; j++) {
            if (q + j < e2) {
                float fx = __uint_as_float(dd[j].y);
                float fy = __uint_as_float(dd[j].z);
                acc += (1.0f - fy) * ((1.0f - fx) * z[j][0] + fx * z[j][1])
                     +         fy  * ((1.0f - fx) * z[j][2] + fx * z[j][3]);
            }
        }
    }

    // finalize: mean + root term + bias, single coalesced store
    float xv = x[(size_t)n * 32 + lane];
    float rt = 0.0f;
#pragma unroll
    for (int i = 0; i < 32; i++) {
        float xi = __shfl_sync(0xffffffffu, xv, i);
        rt += xi * sR[i * 32 + lane];
    }
    float deg = fmaxf((float)(e2 - s), 1.0f);
    out[(size_t)n * 32 + lane] = acc / deg + rt + sB[lane];
}

// ---------------- launch ----------------
extern "C" void kernel_launch(void* const* d_in, const int* in_sizes, int n_in,
                              void* d_out, int out_size) {
    const float* x      = (const float*)d_in[0];
    const void*  ei     = d_in[1];
    const float* pseudo = (const float*)d_in[2];
    const float* weight = (const float*)d_in[3];
    const float* rootw  = (const float*)d_in[4];
    const float* bias   = (const float*)d_in[5];
    float*       out    = (float*)d_out;

    int N  = in_sizes[0] / 32;
    int E  = in_sizes[2] / 2;
    int N1 = N + 1;
    int nsb = (N1 + 1023) / 1024;   // scan blocks (98 for N=100000)

    k_detect<<<1, 256>>>((const unsigned int*)ei, 2 * E);
    k_zeroh<<<(N1 + 255) / 256, 256>>>(N1);
    k_hist<<<(E + 255) / 256, 256>>>(ei, E);
    kA_bsum<<<nsb, 1024>>>(N1);
    kB_scan<<<1, 256>>>(nsb);
    kC_scan<<<nsb, 1024>>>(N1);
    k_scatter<<<(E + 255) / 256, 256>>>(ei, pseudo, E);

    k_prep<<<(KTOT * 1024 + 255) / 256, 256>>>(weight);
    cudaFuncSetAttribute(k_zgemm_mma, cudaFuncAttributeMaxDynamicSharedMemorySize, ZG_SMEM);
    dim3 zg((N + 127) / 128, 2);
    k_zgemm_mma<<<zg, 256, ZG_SMEM>>>(x, N);

    k_edge_csr<<<(N + 7) / 8, 256>>>(x, rootw, bias, out, N);
}

// round 12
// speedup vs baseline: 2.7000x; 1.1646x over previous
#include <cuda_runtime.h>
#include <cuda_fp16.h>
#include <stdint.h>

// SplineConv: N=100000, E=1.6M, DIM=2, K=5, deg-1 open spline, M_in=M_out=32, K_TOT=25.
#define MAXN 100000
#define MAXE 1600000
#define KTOT 25
#define KM   800    // KTOT*32 Z-channels per node

// ---------------- device scratch (allocation-free) ----------------
__device__ __half g_Zh[(size_t)MAXN * KM];   // 160 MB fp16 Z[n, p]  (p = k*32+o)
__device__ __half g_Wh[KTOT * 32 * 32];      // [p=800][i=32] f16  (B operand)
__device__ uint2  g_edesc2[MAXE];            // row-sorted 8B descriptors {col|kidx<<20, fx16|fy16<<16}
__device__ int    g_histN[MAXN + 1];
__device__ int    g_startN[MAXN + 1];        // CSR offsets
__device__ int    g_offN[MAXN + 1];          // scatter cursors
__device__ int    g_bsum[256];
__device__ int    g_bpre[256];
__device__ int    g_is64;

__device__ __forceinline__ uint32_t smem_u32(const void* p) {
    uint32_t a;
    asm("{ .reg .u64 t; cvta.to.shared.u64 t, %1; cvt.u32.u64 %0, t; }" : "=r"(a) : "l"(p));
    return a;
}
__device__ __forceinline__ void ldsm_x4(uint32_t addr, uint32_t* r) {
    asm volatile("ldmatrix.sync.aligned.m8n8.x4.shared.b16 {%0,%1,%2,%3}, [%4];"
        : "=r"(r[0]), "=r"(r[1]), "=r"(r[2]), "=r"(r[3]) : "r"(addr));
}
__device__ __forceinline__ void mma16816(float* d, const uint32_t* a, uint32_t b0, uint32_t b1) {
    asm volatile("mma.sync.aligned.m16n8k16.row.col.f32.f16.f16.f32 "
        "{%0,%1,%2,%3}, {%4,%5,%6,%7}, {%8,%9}, {%0,%1,%2,%3};"
        : "+f"(d[0]), "+f"(d[1]), "+f"(d[2]), "+f"(d[3])
        : "r"(a[0]), "r"(a[1]), "r"(a[2]), "r"(a[3]), "r"(b0), "r"(b1));
}
__device__ __forceinline__ uint32_t packh2(float lo, float hi) {
    uint32_t r;
    asm("cvt.rn.f16x2.f32 %0, %1, %2;" : "=r"(r) : "f"(hi), "f"(lo));
    return r;
}

// ---------------- dtype detection ----------------
__global__ void k_detect(const unsigned int* __restrict__ w, int nwords) {
    __shared__ int nz;
    if (threadIdx.x == 0) nz = 0;
    __syncthreads();
    int lim = nwords < 4096 ? nwords : 4096;
    int any = 0;
    for (int i = 1 + 2 * (int)threadIdx.x; i < lim; i += 2 * (int)blockDim.x)
        if (w[i] != 0u) any = 1;
    if (any) atomicOr(&nz, 1);
    __syncthreads();
    if (threadIdx.x == 0) g_is64 = (nz == 0) ? 1 : 0;
}

// ---------------- zero per-node histogram ----------------
__global__ void k_zeroh(int N1) {
    int i = blockIdx.x * blockDim.x + threadIdx.x;
    if (i < N1) g_histN[i] = 0;
}

// ---------------- per-node degree histogram (100k spread atomics) ----------------
__global__ __launch_bounds__(256)
void k_hist(const void* __restrict__ ei, int E) {
    int e = blockIdx.x * blockDim.x + threadIdx.x;
    if (e >= E) return;
    int r;
    if (g_is64) r = (int)((const long long*)ei)[e];
    else        r = ((const int*)ei)[e];
    atomicAdd(&g_histN[r], 1);
}

// ---------------- multi-block scan (A: block sums, B: scan sums, C: local scan) ----------------
__global__ void kA_bsum(int N1) {
    __shared__ int ws[32];
    int t = threadIdx.x;
    int i = blockIdx.x * 1024 + t;
    int v = (i < N1) ? g_histN[i] : 0;
    for (int o = 16; o > 0; o >>= 1) v += __shfl_down_sync(0xffffffffu, v, o);
    if ((t & 31) == 0) ws[t >> 5] = v;
    __syncthreads();
    if (t < 32) {
        int s = ws[t];
        for (int o = 16; o > 0; o >>= 1) s += __shfl_down_sync(0xffffffffu, s, o);
        if (t == 0) g_bsum[blockIdx.x] = s;
    }
}
__global__ void kB_scan(int nsb) {
    __shared__ int ws[8];
    int t = threadIdx.x;
    int v = (t < nsb) ? g_bsum[t] : 0;
    int lane = t & 31, wid = t >> 5;
    int s = v;
    for (int o = 1; o < 32; o <<= 1) {
        int u = __shfl_up_sync(0xffffffffu, s, o);
        if (lane >= o) s += u;
    }
    if (lane == 31) ws[wid] = s;
    __syncthreads();
    if (wid == 0 && lane < 8) {
        int x2 = ws[lane];
        for (int o = 1; o < 8; o <<= 1) {
            int u = __shfl_up_sync(0xffu, x2, o);
            if (lane >= o) x2 += u;
        }
        ws[lane] = x2;
    }
    __syncthreads();
    int incl = s + (wid > 0 ? ws[wid - 1] : 0);
    if (t < nsb) g_bpre[t] = incl - v;
}
__global__ void kC_scan(int N1) {
    __shared__ int ws[32];
    int t = threadIdx.x;
    int i = blockIdx.x * 1024 + t;
    int v = (i < N1) ? g_histN[i] : 0;
    int lane = t & 31, wid = t >> 5;
    int s = v;
    for (int o = 1; o < 32; o <<= 1) {
        int u = __shfl_up_sync(0xffffffffu, s, o);
        if (lane >= o) s += u;
    }
    if (lane == 31) ws[wid] = s;
    __syncthreads();
    if (wid == 0) {
        int x2 = ws[lane];
        for (int o = 1; o < 32; o <<= 1) {
            int u = __shfl_up_sync(0xffffffffu, x2, o);
            if (lane >= o) x2 += u;
        }
        ws[lane] = x2;
    }
    __syncthreads();
    int excl = s - v + (wid > 0 ? ws[wid - 1] : 0) + g_bpre[blockIdx.x];
    if (i < N1) { g_startN[i] = excl; g_offN[i] = excl; }
}

// ---------------- scatter: compute 8B descriptor, counting-sort by row ----------------
__global__ __launch_bounds__(256)
void k_scatter(const void* __restrict__ ei, const float* __restrict__ pseudo, int E) {
    int e = blockIdx.x * blockDim.x + threadIdx.x;
    if (e >= E) return;
    int r, c;
    if (g_is64) {
        const long long* p = (const long long*)ei;
        r = (int)p[e]; c = (int)p[(size_t)E + e];
    } else {
        const int* p = (const int*)ei;
        r = p[e]; c = p[E + e];
    }
    float2 ps = ((const float2*)pseudo)[e];
    float px = ps.x * 4.0f, py = ps.y * 4.0f;   // scale = K-1 (open spline)
    float lx = fminf(fmaxf(floorf(px), 0.0f), 3.0f);
    float ly = fminf(fmaxf(floorf(py), 0.0f), 3.0f);
    int kidx = (int)ly * 5 + (int)lx;           // 0..18
    uint32_t fxu = (uint32_t)((px - lx) * 65535.0f + 0.5f);
    uint32_t fyu = (uint32_t)((py - ly) * 65535.0f + 0.5f);
    int pos = atomicAdd(&g_offN[r], 1);         // 100k spread cursors
    g_edesc2[pos] = make_uint2((uint32_t)c | ((uint32_t)kidx << 20),
                               fxu | (fyu << 16));
}

// ---------------- W transpose+convert: g_Wh[p][i] = W[k,i,o], p=k*32+o ----------------
__global__ void k_prep(const float* __restrict__ w) {
    int t = blockIdx.x * blockDim.x + threadIdx.x;
    if (t >= KTOT * 1024) return;
    int p = t >> 5, i = t & 31;
    int k = p >> 5, o = p & 31;
    g_Wh[t] = __float2half(w[k * 1024 + i * 32 + o]);
}

// ---------------- Z = x @ Wt via mma.sync m16n8k16, split-N over gridDim.y ----------------
#define NB_COLS 400
#define SB_OFF  10240                    // A: 128*80
#define ZG_SMEM (10240 + NB_COLS * 80)   // + B: 400*80 = 42240

__global__ __launch_bounds__(256, 4)
void k_zgemm_mma(const float* __restrict__ x, int N) {
    extern __shared__ __align__(128) char smem[];
    char* sA = smem;
    char* sB = smem + SB_OFF;
    int tid = threadIdx.x;
    int n0 = blockIdx.x * 128;
    int colbase = blockIdx.y * NB_COLS;

    for (int g = tid; g < NB_COLS * 4; g += 256) {
        int row = g >> 2, sub = g & 3;
        *(uint4*)(sB + row * 80 + sub * 16) =
            *(const uint4*)(g_Wh + (colbase + row) * 32 + sub * 8);
    }
    for (int g = tid; g < 512; g += 256) {
        int row = g >> 2, sub = g & 3;
        int n = n0 + row;
        uint4 hv = make_uint4(0, 0, 0, 0);
        if (n < N) {
            const float4* xp = (const float4*)(x + (size_t)n * 32 + sub * 8);
            float4 a = xp[0], b = xp[1];
            hv.x = packh2(a.x, a.y);
            hv.y = packh2(a.z, a.w);
            hv.z = packh2(b.x, b.y);
            hv.w = packh2(b.z, b.w);
        }
        *(uint4*)(sA + row * 80 + sub * 16) = hv;
    }
    __syncthreads();

    int wid = tid >> 5, lane = tid & 31;
    int m0 = wid * 16;
    int r = lane & 7, sel = lane >> 3;

    uint32_t aaddr = smem_u32(sA + (m0 + r + ((sel & 1) ? 8 : 0)) * 80 + (sel >> 1) * 16);
    uint32_t a[8];
    ldsm_x4(aaddr,      a);
    ldsm_x4(aaddr + 32, a + 4);

    uint32_t sBu  = smem_u32(sB);
    uint32_t bofs = (r + ((sel >> 1) ? 8 : 0)) * 80 + (sel & 1) * 16;

    int mrow  = lane >> 2;
    int ncol0 = (lane & 3) * 2;
    int node_lo = n0 + m0 + mrow;
    int node_hi = node_lo + 8;
    __half* z_lo = g_Zh + (size_t)node_lo * KM + colbase;
    __half* z_hi = g_Zh + (size_t)node_hi * KM + colbase;
    bool ok_lo = node_lo < N, ok_hi = node_hi < N;

    for (int nb = 0; nb < NB_COLS; nb += 16) {
        uint32_t baddr = sBu + nb * 80 + bofs;
        uint32_t b[8];
        ldsm_x4(baddr,      b);
        ldsm_x4(baddr + 32, b + 4);

        float acc0[4] = {0.f, 0.f, 0.f, 0.f};
        float acc1[4] = {0.f, 0.f, 0.f, 0.f};
        mma16816(acc0, a,     b[0], b[1]);
        mma16816(acc0, a + 4, b[4], b[5]);
        mma16816(acc1, a,     b[2], b[3]);
        mma16816(acc1, a + 4, b[6], b[7]);

        if (ok_lo) {
            *(uint32_t*)(z_lo + nb + ncol0)     = packh2(acc0[0], acc0[1]);
            *(uint32_t*)(z_lo + nb + 8 + ncol0) = packh2(acc1[0], acc1[1]);
        }
        if (ok_hi) {
            *(uint32_t*)(z_hi + nb + ncol0)     = packh2(acc0[2], acc0[3]);
            *(uint32_t*)(z_hi + nb + 8 + ncol0) = packh2(acc1[2], acc1[3]);
        }
    }
}

// ---------------- fused CSR edge + finalize: warp/node, 2 edges per instruction ----------------
// Half-warp h (lanes 16h..16h+15) processes its own edges; lane sl handles
// channels {2sl, 2sl+1} as half2. After the loop, shfl_xor(16) merges halves.
__global__ __launch_bounds__(256)
void k_edge_csr(const float* __restrict__ x, const float* __restrict__ rootw,
                const float* __restrict__ bias, float* __restrict__ out, int N) {
    __shared__ float sR[1024];
    __shared__ float sB[32];
    int tid = threadIdx.x;
    for (int i = tid; i < 1024; i += 256) sR[i] = rootw[i];
    if (tid < 32) sB[tid] = bias[tid];
    __syncthreads();

    int lane = tid & 31, wid = tid >> 5;
    int n = blockIdx.x * 8 + wid;
    if (n >= N) return;

    int h  = lane >> 4;          // half-warp id (edge slot)
    int sl = lane & 15;          // sub-lane: channels 2sl, 2sl+1

    int s   = g_startN[n];
    int e2  = g_startN[n + 1];
    int deg = e2 - s;
    const float inv16 = 1.0f / 65535.0f;

    float accx = 0.0f, accy = 0.0f;
    int niter = (deg + 7) >> 3;          // 8 edges per iteration (4 per half)
    for (int it = 0; it < niter; it++) {
        int qb = s + it * 8 + h * 4;
        uint2 dd[4];
#pragma unroll
        for (int j = 0; j < 4; j++) {
            int e = qb + j; if (e > e2 - 1) e = e2 - 1;
            dd[j] = g_edesc2[e];
        }
        uint32_t t0[4], t1[4], t2[4], t3[4];
#pragma unroll
        for (int j = 0; j < 4; j++) {
            const __half* zb = g_Zh + (size_t)(dd[j].x & 0xFFFFFu) * KM
                             + ((dd[j].x >> 20) << 5) + 2 * sl;
            t0[j] = *(const uint32_t*)(zb);        // taps: 2 channels each
            t1[j] = *(const uint32_t*)(zb + 32);
            t2[j] = *(const uint32_t*)(zb + 160);
            t3[j] = *(const uint32_t*)(zb + 192);
        }
#pragma unroll
        for (int j = 0; j < 4; j++) {
            if (qb + j < e2) {
                float fx = (float)(dd[j].y & 0xFFFFu) * inv16;
                float fy = (float)(dd[j].y >> 16)     * inv16;
                float w00 = (1.0f - fx) * (1.0f - fy);
                float w10 = fx * (1.0f - fy);
                float w01 = (1.0f - fx) * fy;
                float w11 = fx * fy;
                float2 z0 = __half22float2(*(__half2*)&t0[j]);
                float2 z1 = __half22float2(*(__half2*)&t1[j]);
                float2 z2 = __half22float2(*(__half2*)&t2[j]);
                float2 z3 = __half22float2(*(__half2*)&t3[j]);
                accx += w00 * z0.x + w10 * z1.x + w01 * z2.x + w11 * z3.x;
                accy += w00 * z0.y + w10 * z1.y + w01 * z2.y + w11 * z3.y;
            }
        }
    }
    // merge the two half-warps (same channel mapping)
    accx += __shfl_xor_sync(0xffffffffu, accx, 16);
    accy += __shfl_xor_sync(0xffffffffu, accy, 16);

    // redistribute: lane c needs channel c (held in lane c>>1 as .x/.y)
    float ax = __shfl_sync(0xffffffffu, accx, lane >> 1);
    float ay = __shfl_sync(0xffffffffu, accy, lane >> 1);
    float aval = (lane & 1) ? ay : ax;

    // finalize: mean + root term + bias
    float xv = x[(size_t)n * 32 + lane];
    float rt = 0.0f;
#pragma unroll
    for (int i = 0; i < 32; i++) {
        float xi = __shfl_sync(0xffffffffu, xv, i);
        rt += xi * sR[i * 32 + lane];
    }
    float degf = fmaxf((float)deg, 1.0f);
    out[(size_t)n * 32 + lane] = aval / degf + rt + sB[lane];
}

// ---------------- launch ----------------
extern "C" void kernel_launch(void* const* d_in, const int* in_sizes, int n_in,
                              void* d_out, int out_size) {
    const float* x      = (const float*)d_in[0];
    const void*  ei     = d_in[1];
    const float* pseudo = (const float*)d_in[2];
    const float* weight = (const float*)d_in[3];
    const float* rootw  = (const float*)d_in[4];
    const float* bias   = (const float*)d_in[5];
    float*       out    = (float*)d_out;

    int N  = in_sizes[0] / 32;
    int E  = in_sizes[2] / 2;
    int N1 = N + 1;
    int nsb = (N1 + 1023) / 1024;

    k_detect<<<1, 256>>>((const unsigned int*)ei, 2 * E);
    k_zeroh<<<(N1 + 255) / 256, 256>>>(N1);
    k_hist<<<(E + 255) / 256, 256>>>(ei, E);
    kA_bsum<<<nsb, 1024>>>(N1);
    kB_scan<<<1, 256>>>(nsb);
    kC_scan<<<nsb, 1024>>>(N1);
    k_scatter<<<(E + 255) / 256, 256>>>(ei, pseudo, E);

    k_prep<<<(KTOT * 1024 + 255) / 256, 256>>>(weight);
    cudaFuncSetAttribute(k_zgemm_mma, cudaFuncAttributeMaxDynamicSharedMemorySize, ZG_SMEM);
    dim3 zg((N + 127) / 128, 2);
    k_zgemm_mma<<<zg, 256, ZG_SMEM>>>(x, N);

    k_edge_csr<<<(N + 7) / 8, 256>>>(x, rootw, bias, out, N);
}